// round 1
// baseline (speedup 1.0000x reference)
#include <cuda_runtime.h>
#include <math.h>

#define N_    64
#define C_    512
#define HW_   1024
#define K_    64
#define ALPHA_ 50.0f
#define EPS_  1e-12f

// scratch: soft-assign a [N,K,HW]  (16 MB, static device array — allowed)
__device__ float g_a[(size_t)N_ * K_ * HW_];
// column-normalized projection weight [C,K]
__device__ float g_Wn[C_ * K_];

// ---------------------------------------------------------------------------
// K0: Wn[:,k] = W[:,k] / max(||W[:,k]||, eps)
// ---------------------------------------------------------------------------
__global__ void wnorm_kernel(const float* __restrict__ w) {
    int k   = blockIdx.x;     // 64 blocks
    int tid = threadIdx.x;    // 256 threads
    __shared__ float red[256];
    float ss = 0.f;
    for (int c = tid; c < C_; c += 256) { float v = w[c * K_ + k]; ss += v * v; }
    red[tid] = ss; __syncthreads();
    for (int s = 128; s > 0; s >>= 1) { if (tid < s) red[tid] += red[tid + s]; __syncthreads(); }
    float inv = 1.f / fmaxf(sqrtf(red[0]), EPS_);
    for (int c = tid; c < C_; c += 256) g_Wn[c * K_ + k] = w[c * K_ + k] * inv;
}

// ---------------------------------------------------------------------------
// K1: per (n, 32-wide hw tile):
//   load x tile [C,32] -> smem, compute per-hw inv norms,
//   write feature[n,hw,c] (normalized, transposed),
//   GEMM1 logits[k,j] = inv[j] * sum_c x[c,j]*Wn[c,k]  -> sa_logits (raw),
//   softmax over k with (L + bias)*ALPHA -> g_a
// smem layout (floats): xt[512*33] | ws[64*64] | ls[64*33] | inv[32] | part[256]
// ---------------------------------------------------------------------------
#define SMEM1_FLOATS (C_ * 33 + 64 * 64 + K_ * 33 + 32 + 256)

__global__ void __launch_bounds__(256, 2)
k1_kernel(const float* __restrict__ x, const float* __restrict__ bias,
          float* __restrict__ feature, float* __restrict__ sa_out) {
    extern __shared__ float sm[];
    float* xt   = sm;                  // stride 33 (pad kills transpose conflicts)
    float* ws   = xt + C_ * 33;        // 16B-aligned (16896 % 4 == 0)
    float* ls   = ws + 64 * 64;
    float* inv  = ls + K_ * 33;
    float* part = inv + 32;

    int b   = blockIdx.x;              // N_*32 blocks
    int n   = b >> 5;
    int hw0 = (b & 31) * 32;
    int tid = threadIdx.x;             // 256

    // --- load x tile, coalesced along hw ---
    const float* xp = x + (size_t)n * C_ * HW_ + hw0;
    for (int idx = tid; idx < C_ * 32; idx += 256) {
        int c = idx >> 5, j = idx & 31;
        xt[c * 33 + j] = xp[(size_t)c * HW_ + j];
    }
    __syncthreads();

    // --- per-hw channel norms ---
    {
        int j = tid & 31, t = tid >> 5;
        float ss = 0.f;
        for (int c = t; c < C_; c += 8) { float v = xt[c * 33 + j]; ss += v * v; }
        part[tid] = ss;
    }
    __syncthreads();
    if (tid < 32) {
        float ss = 0.f;
        for (int t = 0; t < 8; t++) ss += part[t * 32 + tid];
        inv[tid] = 1.f / fmaxf(sqrtf(ss), EPS_);
    }
    __syncthreads();

    // --- write feature[n, hw0+j, c] (coalesced along c; strided smem read is pad-safe) ---
    float* fp = feature + ((size_t)n * HW_ + hw0) * C_;
    for (int idx = tid; idx < 32 * C_; idx += 256) {
        int j = idx >> 9, c = idx & (C_ - 1);
        fp[(size_t)j * C_ + c] = xt[c * 33 + j] * inv[j];
    }

    // --- GEMM1: 4k x 2j register tile per thread ---
    int kg = tid & 15;        int k4 = kg * 4;       // 16 groups * 4 k = 64
    int jg = tid >> 4;        int j2 = jg * 2;       // 16 groups * 2 j = 32
    float acc[4][2] = {};
    for (int cc = 0; cc < C_; cc += 64) {
        __syncthreads();                              // protect ws reuse
        for (int idx = tid; idx < 64 * 64; idx += 256) ws[idx] = g_Wn[cc * K_ + idx];
        __syncthreads();
        const float4* ws4 = reinterpret_cast<const float4*>(ws);
        #pragma unroll 4
        for (int ci = 0; ci < 64; ci++) {
            float4 wv = ws4[ci * 16 + kg];
            float xv0 = xt[(cc + ci) * 33 + j2];
            float xv1 = xt[(cc + ci) * 33 + j2 + 1];
            acc[0][0] += wv.x * xv0; acc[0][1] += wv.x * xv1;
            acc[1][0] += wv.y * xv0; acc[1][1] += wv.y * xv1;
            acc[2][0] += wv.z * xv0; acc[2][1] += wv.z * xv1;
            acc[3][0] += wv.w * xv0; acc[3][1] += wv.w * xv1;
        }
    }
    __syncthreads();
    #pragma unroll
    for (int q = 0; q < 4; q++)
        #pragma unroll
        for (int p = 0; p < 2; p++)
            ls[(k4 + q) * 33 + j2 + p] = acc[q][p] * inv[j2 + p];
    __syncthreads();

    // --- raw sa_logits out ---
    float* sp = sa_out + (size_t)n * K_ * HW_ + hw0;
    for (int idx = tid; idx < K_ * 32; idx += 256) {
        int k = idx >> 5, j = idx & 31;
        sp[(size_t)k * HW_ + j] = ls[k * 33 + j];
    }
    __syncthreads();

    // --- softmax over k per column j (temp ALPHA, + bias) ---
    if (tid < 32) {
        int j = tid;
        float m = -INFINITY;
        for (int k = 0; k < K_; k++) {
            float v = (ls[k * 33 + j] + bias[k]) * ALPHA_;
            m = fmaxf(m, v);
        }
        float s = 0.f;
        for (int k = 0; k < K_; k++) {
            float e = expf((ls[k * 33 + j] + bias[k]) * ALPHA_ - m);
            ls[k * 33 + j] = e; s += e;
        }
        float is = 1.f / s;
        for (int k = 0; k < K_; k++) ls[k * 33 + j] *= is;
    }
    __syncthreads();

    float* ap = g_a + (size_t)n * K_ * HW_ + hw0;
    for (int idx = tid; idx < K_ * 32; idx += 256) {
        int k = idx >> 5, j = idx & 31;
        ap[(size_t)k * HW_ + j] = ls[k * 33 + j];
    }
}

// ---------------------------------------------------------------------------
// K2: per (n, 16-k tile): vlad_raw[k,c] = sum_hw a[k,hw]*feature[hw,c]
//                         - (sum_hw a[k,hw]) * W[c,k]; then row-L2-normalize.
// smem (floats): fs[32*512] | as[16*32] | red[1024] | invr[16]
// ---------------------------------------------------------------------------
#define SMEM2_FLOATS (32 * C_ + 16 * 32 + 1024 + 16)

__global__ void __launch_bounds__(256, 2)
k2_kernel(const float* __restrict__ w, const float* __restrict__ feature,
          float* __restrict__ vlad) {
    extern __shared__ float sm[];
    float* fs   = sm;                  // [32][512]
    float* as   = fs + 32 * C_;        // [16][32]
    float* red  = as + 16 * 32;        // [256][4]
    float* invr = red + 1024;          // [16]

    int b   = blockIdx.x;              // N_*4 blocks
    int n   = b >> 2;
    int k0  = (b & 3) * 16;
    int tid = threadIdx.x;
    int cb  = tid & 63;                // c = cb + 64p
    int kg  = tid >> 6;                // rows kg*4 + q

    float acc[4][8] = {};
    float rs[4] = {0.f, 0.f, 0.f, 0.f};   // deterministic asum (redundant per 64-thread group)

    for (int hw = 0; hw < HW_; hw += 32) {
        __syncthreads();
        for (int idx = tid; idx < 32 * C_; idx += 256) {
            int j = idx >> 9, c = idx & (C_ - 1);
            fs[idx] = feature[((size_t)n * HW_ + hw + j) * C_ + c];
        }
        for (int idx = tid; idx < 16 * 32; idx += 256) {
            int kk = idx >> 5, jj = idx & 31;
            as[idx] = g_a[(size_t)n * K_ * HW_ + (size_t)(k0 + kk) * HW_ + hw + jj];
        }
        __syncthreads();
        #pragma unroll 4
        for (int j = 0; j < 32; j++) {
            float av[4], fv[8];
            #pragma unroll
            for (int q = 0; q < 4; q++) { av[q] = as[(kg * 4 + q) * 32 + j]; rs[q] += av[q]; }
            #pragma unroll
            for (int p = 0; p < 8; p++) fv[p] = fs[j * C_ + cb + 64 * p];
            #pragma unroll
            for (int q = 0; q < 4; q++)
                #pragma unroll
                for (int p = 0; p < 8; p++)
                    acc[q][p] += av[q] * fv[p];
        }
    }
    __syncthreads();

    // centroid subtract (unnormalized W!), row sum-of-squares
    float v[4][8];
    #pragma unroll
    for (int q = 0; q < 4; q++) {
        int k = k0 + kg * 4 + q;
        float ssq = 0.f;
        #pragma unroll
        for (int p = 0; p < 8; p++) {
            int c = cb + 64 * p;
            float t = acc[q][p] - rs[q] * w[(size_t)c * K_ + k];
            v[q][p] = t;
            ssq += t * t;
        }
        red[tid * 4 + q] = ssq;
    }
    __syncthreads();
    if (tid < 16) {
        int g = tid >> 2, q = tid & 3;
        float ss = 0.f;
        for (int i = 0; i < 64; i++) ss += red[(g * 64 + i) * 4 + q];
        invr[tid] = 1.f / fmaxf(sqrtf(ss), EPS_);
    }
    __syncthreads();
    #pragma unroll
    for (int q = 0; q < 4; q++) {
        int r = kg * 4 + q;
        float iv = invr[r];
        #pragma unroll
        for (int p = 0; p < 8; p++)
            vlad[(size_t)n * K_ * C_ + (size_t)(k0 + r) * C_ + cb + 64 * p] = v[q][p] * iv;
    }
}

// ---------------------------------------------------------------------------
extern "C" void kernel_launch(void* const* d_in, const int* in_sizes, int n_in,
                              void* d_out, int out_size) {
    const float* x    = (const float*)d_in[0];   // [64,512,32,32]
    const float* w    = (const float*)d_in[1];   // [512,64]
    const float* bias = (const float*)d_in[2];   // [64]
    float* out  = (float*)d_out;
    float* vlad = out;                                    // [64, 64*512]
    float* sa   = out + (size_t)N_ * K_ * C_;             // [64, 64, 1024]
    float* feat = sa  + (size_t)N_ * K_ * HW_;            // [64, 1024, 512]

    cudaFuncSetAttribute(k1_kernel, cudaFuncAttributeMaxDynamicSharedMemorySize,
                         SMEM1_FLOATS * (int)sizeof(float));
    cudaFuncSetAttribute(k2_kernel, cudaFuncAttributeMaxDynamicSharedMemorySize,
                         SMEM2_FLOATS * (int)sizeof(float));

    wnorm_kernel<<<K_, 256>>>(w);
    k1_kernel<<<N_ * 32, 256, SMEM1_FLOATS * sizeof(float)>>>(x, bias, feat, sa);
    k2_kernel<<<N_ * 4, 256, SMEM2_FLOATS * sizeof(float)>>>(w, feat, vlad);
}